// round 6
// baseline (speedup 1.0000x reference)
#include <cuda_runtime.h>
#include <cuda_bf16.h>
#include <cstdint>
#include <math.h>

#define NDIN 25
#define NDP  128
#define NROWS (256*2048)
#define TILE_M 128
#define NTILES (NROWS/TILE_M)   // 4096
#define NTHREADS 256
#define GRID 148

// ---------------- SMEM layout (byte offsets) ----------------
#define OFF_X     0        // 12800 B  (128 rows x 25 f32)
#define OFF_XNHI  12800    // 10240 B  (128 rows x 80B: 32 bf16, 80B row stride)
#define OFF_XNLO  23040    // 10240 B
#define OFF_W1F   33280    // 16384 B  [s2][j16][t32] uint4 = (bh0,bh1,bl0,bl1)
#define OFF_W2F   49664    // 65536 B  [s8][j16][t32] uint4
#define OFF_B1    115200   // 512
#define OFF_B2    115712   // 512
#define OFF_G     116224   // 128
#define OFF_BETA  116352   // 128
#define SMEM_TOTAL 116480

__device__ __forceinline__ uint32_t smem_u32(const void* p) {
    uint32_t a;
    asm("{ .reg .u64 t; cvta.to.shared.u64 t, %1; cvt.u32.u64 %0, t; }" : "=r"(a) : "l"(p));
    return a;
}

__device__ __forceinline__ void ldsm4(uint32_t* r, uint32_t addr) {
    asm volatile("ldmatrix.sync.aligned.m8n8.x4.shared.b16 {%0,%1,%2,%3}, [%4];"
                 : "=r"(r[0]), "=r"(r[1]), "=r"(r[2]), "=r"(r[3]) : "r"(addr));
}

__device__ __forceinline__ void mma_bf16(float* c, const uint32_t* a, uint32_t b0, uint32_t b1) {
    asm volatile("mma.sync.aligned.m16n8k16.row.col.f32.bf16.bf16.f32 "
                 "{%0,%1,%2,%3}, {%4,%5,%6,%7}, {%8,%9}, {%0,%1,%2,%3};"
                 : "+f"(c[0]), "+f"(c[1]), "+f"(c[2]), "+f"(c[3])
                 : "r"(a[0]), "r"(a[1]), "r"(a[2]), "r"(a[3]), "r"(b0), "r"(b1));
}

__device__ __forceinline__ void cp16(uint32_t saddr, const void* g) {
    asm volatile("cp.async.ca.shared.global [%0], [%1], 16;" :: "r"(saddr), "l"(g));
}
#define CP_COMMIT() asm volatile("cp.async.commit_group;" ::: "memory")
#define CP_WAIT0()  asm volatile("cp.async.wait_group 0;" ::: "memory")

// pack two f32->bf16 into one u32: low half = first arg
__device__ __forceinline__ uint32_t pk2(float f_lo, float f_hi) {
    uint32_t r;
    asm("cvt.rn.bf16x2.f32 %0, %1, %2;" : "=r"(r) : "f"(f_hi), "f"(f_lo));
    return r;
}

// GELU with erf via Abramowitz-Stegun 7.1.26 (|eps_erf| <= 1.5e-7)
__device__ __forceinline__ float gelu_f(float v) {
    float z = fabsf(v) * 0.70710678118654752440f;
    float t = __fdividef(1.0f, fmaf(0.3275911f, z, 1.0f));
    float p = t * fmaf(t, fmaf(t, fmaf(t, fmaf(t, 1.061405429f, -1.453152027f),
                                       1.421413741f), -0.284496736f), 0.254829592f);
    float e = __expf(-z * z);
    float erfv = fmaf(-p, e, 1.0f);
    float erfs = (v < 0.0f) ? -erfv : erfv;
    return 0.5f * v * (1.0f + erfs);
}

__device__ __forceinline__ float bf16_resid(float v) {
    __nv_bfloat16 h = __float2bfloat16_rn(v);
    return v - __bfloat162float(h);
}

__global__ __launch_bounds__(NTHREADS, 1)
void ip_mma_kernel(const float* __restrict__ x,
                   const float* __restrict__ ln_g,
                   const float* __restrict__ ln_b,
                   const float* __restrict__ w1,
                   const float* __restrict__ b1,
                   const float* __restrict__ w2,
                   const float* __restrict__ b2,
                   float* __restrict__ out) {
    extern __shared__ char smem[];
    const uint32_t sb = smem_u32(smem);
    const int tid = threadIdx.x;
    const int lane = tid & 31;
    const int wid = tid >> 5;

    float* b1s = reinterpret_cast<float*>(smem + OFF_B1);
    float* b2s = reinterpret_cast<float*>(smem + OFF_B2);
    float* gs  = reinterpret_cast<float*>(smem + OFF_G);
    float* bs  = reinterpret_cast<float*>(smem + OFF_BETA);

    if (tid < 128) { b1s[tid] = b1[tid]; b2s[tid] = b2[tid]; }
    if (tid < NDIN) { gs[tid] = ln_g[tid]; bs[tid] = ln_b[tid]; }

    // ---- stage w1 fragments: B[n][k]=w1[k][n], interleaved hi/lo uint4 ----
    uint4* w1f = reinterpret_cast<uint4*>(smem + OFF_W1F);
    for (int idx = tid; idx < 2 * 16 * 32; idx += NTHREADS) {
        int t = idx & 31, j = (idx >> 5) & 15, s = idx >> 9;
        int n = 8 * j + (t >> 2);
        int k0 = 16 * s + 2 * (t & 3);
        int kk[4] = {k0, k0 + 1, k0 + 8, k0 + 9};
        float v[4], r[4];
        #pragma unroll
        for (int q = 0; q < 4; q++) {
            v[q] = (kk[q] < NDIN) ? w1[kk[q] * NDP + n] : 0.0f;
            r[q] = bf16_resid(v[q]);
        }
        uint4 val;
        val.x = pk2(v[0], v[1]);
        val.y = pk2(v[2], v[3]);
        val.z = pk2(r[0], r[1]);
        val.w = pk2(r[2], r[3]);
        w1f[(s * 16 + j) * 32 + t] = val;
    }
    // ---- stage w2 fragments: B[n][k]=w2[k][n], interleaved hi/lo uint4 ----
    uint4* w2f = reinterpret_cast<uint4*>(smem + OFF_W2F);
    for (int idx = tid; idx < 8 * 16 * 32; idx += NTHREADS) {
        int t = idx & 31, j = (idx >> 5) & 15, s = idx >> 9;
        int n = 8 * j + (t >> 2);
        int k0 = 16 * s + 2 * (t & 3);
        float v0 = w2[k0 * NDP + n],       v1 = w2[(k0 + 1) * NDP + n];
        float v2 = w2[(k0 + 8) * NDP + n], v3 = w2[(k0 + 9) * NDP + n];
        uint4 val;
        val.x = pk2(v0, v1);
        val.y = pk2(v2, v3);
        val.z = pk2(bf16_resid(v0), bf16_resid(v1));
        val.w = pk2(bf16_resid(v2), bf16_resid(v3));
        w2f[(s * 16 + j) * 32 + t] = val;
    }
    __syncthreads();

    // per-warp ldmatrix base addresses for xn A-frags (16-row strip)
    const int m0 = wid * 16;
    const uint32_t addrAh = sb + OFF_XNHI + (uint32_t)(m0 + (lane & 15)) * 80 + ((lane >> 4) & 1) * 16;
    const uint32_t addrAl = sb + OFF_XNLO + (uint32_t)(m0 + (lane & 15)) * 80 + ((lane >> 4) & 1) * 16;

    // ---- prologue: prefetch first x tile ----
    {
        const char* src = reinterpret_cast<const char*>(x) + (size_t)blockIdx.x * TILE_M * NDIN * 4;
        #pragma unroll
        for (int k = 0; k < 4; k++) {
            int idx = tid + NTHREADS * k;
            if (idx < 800) cp16(sb + OFF_X + idx * 16, src + idx * 16);
        }
        CP_COMMIT();
    }

    for (int t = blockIdx.x; t < NTILES; t += GRID) {
        CP_WAIT0();
        __syncthreads();   // x tile ready; prior iter's xn reads done

        // ---- LayerNorm + bf16 split -> xn SMEM (threads 0..127, one row each) ----
        if (tid < 128) {
            const float* xr = reinterpret_cast<const float*>(smem + OFF_X) + tid * NDIN;
            float xv[NDIN];
            float s = 0.0f;
            #pragma unroll
            for (int k = 0; k < NDIN; k++) { xv[k] = xr[k]; s += xv[k]; }
            float mu = s * (1.0f / NDIN);
            float vv = 0.0f;
            #pragma unroll
            for (int k = 0; k < NDIN; k++) { float d = xv[k] - mu; vv += d * d; }
            float rstd = rsqrtf(vv * (1.0f / NDIN) + 1e-5f);
            uint32_t* dh = reinterpret_cast<uint32_t*>(smem + OFF_XNHI + tid * 80);
            uint32_t* dl = reinterpret_cast<uint32_t*>(smem + OFF_XNLO + tid * 80);
            #pragma unroll
            for (int c = 0; c < 16; c++) {
                int k0 = 2 * c, k1 = 2 * c + 1;
                float e0 = (k0 < NDIN) ? (xv[k0] - mu) * rstd * gs[k0] + bs[k0] : 0.0f;
                float e1 = (k1 < NDIN) ? (xv[k1] - mu) * rstd * gs[k1] + bs[k1] : 0.0f;
                dh[c] = pk2(e0, e1);
                dl[c] = pk2(bf16_resid(e0), bf16_resid(e1));
            }
        }
        __syncthreads();   // xn ready; x buffer free

        // ---- prefetch next x tile (overlaps all MMA work) ----
        {
            int tn = t + GRID;
            if (tn < NTILES) {
                const char* src = reinterpret_cast<const char*>(x) + (size_t)tn * TILE_M * NDIN * 4;
                #pragma unroll
                for (int k = 0; k < 4; k++) {
                    int idx = tid + NTHREADS * k;
                    if (idx < 800) cp16(sb + OFF_X + idx * 16, src + idx * 16);
                }
            }
            CP_COMMIT();
        }

        // ---- GEMM1: acc = xn @ w1, term-major in j-groups of 4 (ILP) ----
        uint32_t ah[8], al[8];
        ldsm4(ah + 0, addrAh);      ldsm4(ah + 4, addrAh + 32);
        ldsm4(al + 0, addrAl);      ldsm4(al + 4, addrAl + 32);

        float acc[16][4];
        #pragma unroll
        for (int j = 0; j < 16; j++)
            #pragma unroll
            for (int r = 0; r < 4; r++) acc[j][r] = 0.0f;

        const uint4* f1 = reinterpret_cast<const uint4*>(smem + OFF_W1F);
        #pragma unroll
        for (int jg = 0; jg < 4; jg++) {
            uint4 b[2][4];
            #pragma unroll
            for (int s = 0; s < 2; s++)
                #pragma unroll
                for (int jj = 0; jj < 4; jj++)
                    b[s][jj] = f1[(s * 16 + jg * 4 + jj) * 32 + lane];
            // term 1: hi*hi  (8 independent MMAs)
            #pragma unroll
            for (int s = 0; s < 2; s++)
                #pragma unroll
                for (int jj = 0; jj < 4; jj++)
                    mma_bf16(acc[jg * 4 + jj], ah + 4 * s, b[s][jj].x, b[s][jj].y);
            // term 2: hi*lo  (reuse distance 8)
            #pragma unroll
            for (int s = 0; s < 2; s++)
                #pragma unroll
                for (int jj = 0; jj < 4; jj++)
                    mma_bf16(acc[jg * 4 + jj], ah + 4 * s, b[s][jj].z, b[s][jj].w);
            // term 3: lo*hi
            #pragma unroll
            for (int s = 0; s < 2; s++)
                #pragma unroll
                for (int jj = 0; jj < 4; jj++)
                    mma_bf16(acc[jg * 4 + jj], al + 4 * s, b[s][jj].x, b[s][jj].y);
        }

        // ---- bias + GELU + split: C frags -> GEMM2 A frags (registers only) ----
        uint32_t a2h[8][4], a2l[8][4];
        #pragma unroll
        for (int j = 0; j < 16; j++) {
            const float2 bb = *reinterpret_cast<const float2*>(b1s + 8 * j + 2 * (lane & 3));
            float g0 = gelu_f(acc[j][0] + bb.x);
            float g1 = gelu_f(acc[j][1] + bb.y);
            float g2 = gelu_f(acc[j][2] + bb.x);
            float g3 = gelu_f(acc[j][3] + bb.y);
            int s = j >> 1, h = (j & 1) * 2;
            a2h[s][h + 0] = pk2(g0, g1);
            a2h[s][h + 1] = pk2(g2, g3);
            a2l[s][h + 0] = pk2(bf16_resid(g0), bf16_resid(g1));
            a2l[s][h + 1] = pk2(bf16_resid(g2), bf16_resid(g3));
        }

        // ---- GEMM2 in two j-halves, term-major per k-step (ILP) ----
        const uint4* f2 = reinterpret_cast<const uint4*>(smem + OFF_W2F);
        const size_t row0 = (size_t)t * TILE_M + m0 + (lane >> 2);
        #pragma unroll
        for (int half = 0; half < 2; half++) {
            float acc2[8][4];
            #pragma unroll
            for (int j = 0; j < 8; j++)
                #pragma unroll
                for (int r = 0; r < 4; r++) acc2[j][r] = 0.0f;

            #pragma unroll
            for (int s = 0; s < 8; s++) {
                uint4 b[8];
                #pragma unroll
                for (int j8 = 0; j8 < 8; j8++)
                    b[j8] = f2[(s * 16 + half * 8 + j8) * 32 + lane];
                // term 1: hi*hi (8 independent)
                #pragma unroll
                for (int j8 = 0; j8 < 8; j8++)
                    mma_bf16(acc2[j8], a2h[s], b[j8].x, b[j8].y);
                // term 2: hi*lo
                #pragma unroll
                for (int j8 = 0; j8 < 8; j8++)
                    mma_bf16(acc2[j8], a2h[s], b[j8].z, b[j8].w);
                // term 3: lo*hi
                #pragma unroll
                for (int j8 = 0; j8 < 8; j8++)
                    mma_bf16(acc2[j8], a2l[s], b[j8].x, b[j8].y);
            }

            // epilogue for this half: +b2, float2 stores
            #pragma unroll
            for (int j8 = 0; j8 < 8; j8++) {
                int j = 8 * half + j8;
                const float2 bb = *reinterpret_cast<const float2*>(b2s + 8 * j + 2 * (lane & 3));
                int col = 8 * j + 2 * (lane & 3);
                float2 o0 = make_float2(acc2[j8][0] + bb.x, acc2[j8][1] + bb.y);
                float2 o1 = make_float2(acc2[j8][2] + bb.x, acc2[j8][3] + bb.y);
                *reinterpret_cast<float2*>(out + row0 * NDP + col) = o0;
                *reinterpret_cast<float2*>(out + (row0 + 8) * NDP + col) = o1;
            }
        }
    }
}

extern "C" void kernel_launch(void* const* d_in, const int* in_sizes, int n_in,
                              void* d_out, int out_size) {
    (void)in_sizes; (void)n_in; (void)out_size;
    const float* x    = (const float*)d_in[0];
    const float* ln_g = (const float*)d_in[1];
    const float* ln_b = (const float*)d_in[2];
    const float* w1   = (const float*)d_in[3];
    const float* b1   = (const float*)d_in[4];
    const float* w2   = (const float*)d_in[5];
    const float* b2   = (const float*)d_in[6];
    float* out = (float*)d_out;

    cudaFuncSetAttribute(ip_mma_kernel, cudaFuncAttributeMaxDynamicSharedMemorySize, SMEM_TOTAL);
    ip_mma_kernel<<<GRID, NTHREADS, SMEM_TOTAL>>>(x, ln_g, ln_b, w1, b1, w2, b2, out);
}

// round 7
// speedup vs baseline: 1.0858x; 1.0858x over previous
#include <cuda_runtime.h>
#include <cuda_bf16.h>
#include <cstdint>
#include <math.h>

#define NDIN 25
#define NDP  128
#define NROWS (256*2048)
#define TILE_M 128
#define NTILES (NROWS/TILE_M)   // 4096
#define NTHREADS 256
#define GRID 296                // 2 CTAs/SM x 148

// ---------------- SMEM layout (byte offsets) ----------------
#define OFF_X     0        // 12800 B (128 rows x 25 f32, packed)
#define OFF_STAT  12800    // 1024 B  (128 x {mu, rstd})
#define OFF_W1F   13824    // 16384 B [s2][j16][t32] uint4 = (bh0,bh1,bl0,bl1)
#define OFF_W2F   30208    // 65536 B [s8][j16][t32] uint4
#define OFF_B1    95744    // 512
#define OFF_B2    96256    // 512
#define OFF_G     96768    // 128 (32 f32, zero-padded past 24)
#define OFF_BETA  96896    // 128
#define SMEM_TOTAL 97024

__device__ __forceinline__ uint32_t smem_u32(const void* p) {
    uint32_t a;
    asm("{ .reg .u64 t; cvta.to.shared.u64 t, %1; cvt.u32.u64 %0, t; }" : "=r"(a) : "l"(p));
    return a;
}

__device__ __forceinline__ void mma4(float* c, uint32_t a0, uint32_t a1, uint32_t a2, uint32_t a3,
                                     uint32_t b0, uint32_t b1) {
    asm volatile("mma.sync.aligned.m16n8k16.row.col.f32.bf16.bf16.f32 "
                 "{%0,%1,%2,%3}, {%4,%5,%6,%7}, {%8,%9}, {%0,%1,%2,%3};"
                 : "+f"(c[0]), "+f"(c[1]), "+f"(c[2]), "+f"(c[3])
                 : "r"(a0), "r"(a1), "r"(a2), "r"(a3), "r"(b0), "r"(b1));
}

__device__ __forceinline__ void cp16(uint32_t saddr, const void* g) {
    asm volatile("cp.async.ca.shared.global [%0], [%1], 16;" :: "r"(saddr), "l"(g));
}
#define CP_COMMIT() asm volatile("cp.async.commit_group;" ::: "memory")
#define CP_WAIT0()  asm volatile("cp.async.wait_group 0;" ::: "memory")

// pack two f32->bf16: low half = first arg
__device__ __forceinline__ uint32_t pk2(float f_lo, float f_hi) {
    uint32_t r;
    asm("cvt.rn.bf16x2.f32 %0, %1, %2;" : "=r"(r) : "f"(f_hi), "f"(f_lo));
    return r;
}

// GELU, erf via Abramowitz-Stegun 7.1.26 (|eps_erf| <= 1.5e-7)
__device__ __forceinline__ float gelu_f(float v) {
    float z = fabsf(v) * 0.70710678118654752440f;
    float t = __fdividef(1.0f, fmaf(0.3275911f, z, 1.0f));
    float p = t * fmaf(t, fmaf(t, fmaf(t, fmaf(t, 1.061405429f, -1.453152027f),
                                       1.421413741f), -0.284496736f), 0.254829592f);
    float e = __expf(-z * z);
    float erfv = fmaf(-p, e, 1.0f);
    float erfs = (v < 0.0f) ? -erfv : erfv;
    return 0.5f * v * (1.0f + erfs);
}

__device__ __forceinline__ float bf16_resid(float v) {
    __nv_bfloat16 h = __float2bfloat16_rn(v);
    return v - __bfloat162float(h);
}

__global__ __launch_bounds__(NTHREADS, 2)
void ip_mma_kernel(const float* __restrict__ x,
                   const float* __restrict__ ln_g,
                   const float* __restrict__ ln_b,
                   const float* __restrict__ w1,
                   const float* __restrict__ b1,
                   const float* __restrict__ w2,
                   const float* __restrict__ b2,
                   float* __restrict__ out) {
    extern __shared__ char smem[];
    const uint32_t sb = smem_u32(smem);
    const int tid = threadIdx.x;
    const int lane = tid & 31;
    const int wid = tid >> 5;

    float* b1s = reinterpret_cast<float*>(smem + OFF_B1);
    float* b2s = reinterpret_cast<float*>(smem + OFF_B2);
    float* gs  = reinterpret_cast<float*>(smem + OFF_G);
    float* bs  = reinterpret_cast<float*>(smem + OFF_BETA);
    float* Xs  = reinterpret_cast<float*>(smem + OFF_X);
    float* st  = reinterpret_cast<float*>(smem + OFF_STAT);

    if (tid < 128) { b1s[tid] = b1[tid]; b2s[tid] = b2[tid]; }
    if (tid < 32) {
        gs[tid] = (tid < NDIN) ? ln_g[tid] : 0.0f;
        bs[tid] = (tid < NDIN) ? ln_b[tid] : 0.0f;
    }

    // ---- stage w1 fragments: B[n][k]=w1[k][n], interleaved hi/lo uint4 ----
    uint4* w1f = reinterpret_cast<uint4*>(smem + OFF_W1F);
    for (int idx = tid; idx < 2 * 16 * 32; idx += NTHREADS) {
        int t = idx & 31, j = (idx >> 5) & 15, s = idx >> 9;
        int n = 8 * j + (t >> 2);
        int k0 = 16 * s + 2 * (t & 3);
        int kk[4] = {k0, k0 + 1, k0 + 8, k0 + 9};
        float v[4], r[4];
        #pragma unroll
        for (int q = 0; q < 4; q++) {
            v[q] = (kk[q] < NDIN) ? w1[kk[q] * NDP + n] : 0.0f;
            r[q] = bf16_resid(v[q]);
        }
        uint4 val;
        val.x = pk2(v[0], v[1]);
        val.y = pk2(v[2], v[3]);
        val.z = pk2(r[0], r[1]);
        val.w = pk2(r[2], r[3]);
        w1f[(s * 16 + j) * 32 + t] = val;
    }
    // ---- stage w2 fragments: B[n][k]=w2[k][n], interleaved hi/lo uint4 ----
    uint4* w2f = reinterpret_cast<uint4*>(smem + OFF_W2F);
    for (int idx = tid; idx < 8 * 16 * 32; idx += NTHREADS) {
        int t = idx & 31, j = (idx >> 5) & 15, s = idx >> 9;
        int n = 8 * j + (t >> 2);
        int k0 = 16 * s + 2 * (t & 3);
        float v0 = w2[k0 * NDP + n],       v1 = w2[(k0 + 1) * NDP + n];
        float v2 = w2[(k0 + 8) * NDP + n], v3 = w2[(k0 + 9) * NDP + n];
        uint4 val;
        val.x = pk2(v0, v1);
        val.y = pk2(v2, v3);
        val.z = pk2(bf16_resid(v0), bf16_resid(v1));
        val.w = pk2(bf16_resid(v2), bf16_resid(v3));
        w2f[(s * 16 + j) * 32 + t] = val;
    }
    __syncthreads();

    const int m0 = wid * 16;
    const int q2 = 2 * (lane & 3);
    const int rA = m0 + (lane >> 2);    // rows this thread owns in A/C frags
    const int rB = rA + 8;

    // ---- prologue: prefetch first x tile ----
    {
        const char* src = reinterpret_cast<const char*>(x) + (size_t)blockIdx.x * TILE_M * NDIN * 4;
        #pragma unroll
        for (int k = 0; k < 4; k++) {
            int idx = tid + NTHREADS * k;
            if (idx < 800) cp16(sb + OFF_X + idx * 16, src + idx * 16);
        }
        CP_COMMIT();
    }

    for (int t = blockIdx.x; t < NTILES; t += GRID) {
        CP_WAIT0();
        __syncthreads();   // x tile ready

        // ---- LN stats pass: one row per thread (tid<128) ----
        if (tid < 128) {
            const float* xr = Xs + tid * NDIN;
            float xv[NDIN];
            float s = 0.0f;
            #pragma unroll
            for (int k = 0; k < NDIN; k++) { xv[k] = xr[k]; s += xv[k]; }
            float mu = s * (1.0f / NDIN);
            float vv = 0.0f;
            #pragma unroll
            for (int k = 0; k < NDIN; k++) { float d = xv[k] - mu; vv += d * d; }
            st[2 * tid]     = mu;
            st[2 * tid + 1] = rsqrtf(vv * (1.0f / NDIN) + 1e-5f);
        }
        __syncthreads();   // stats ready (X still live)

        // ---- build GEMM1 A-frags directly from X + stats ----
        uint32_t ah[8], al[8];
        {
            const float muA = st[2 * rA], rsA = st[2 * rA + 1];
            const float muB = st[2 * rB], rsB = st[2 * rB + 1];
            #pragma unroll
            for (int s = 0; s < 2; s++) {
                #pragma unroll
                for (int h = 0; h < 2; h++) {
                    int k0 = 16 * s + 8 * h + q2;
                    float g0 = gs[k0], g1 = gs[k0 + 1];
                    float be0 = bs[k0], be1 = bs[k0 + 1];
                    float xa0 = (k0 < NDIN)     ? Xs[rA * NDIN + k0]     : 0.0f;
                    float xa1 = (k0 + 1 < NDIN) ? Xs[rA * NDIN + k0 + 1] : 0.0f;
                    float xb0 = (k0 < NDIN)     ? Xs[rB * NDIN + k0]     : 0.0f;
                    float xb1 = (k0 + 1 < NDIN) ? Xs[rB * NDIN + k0 + 1] : 0.0f;
                    float eA0 = fmaf((xa0 - muA) * rsA, g0, be0);
                    float eA1 = fmaf((xa1 - muA) * rsA, g1, be1);
                    float eB0 = fmaf((xb0 - muB) * rsB, g0, be0);
                    float eB1 = fmaf((xb1 - muB) * rsB, g1, be1);
                    ah[4 * s + 2 * h + 0] = pk2(eA0, eA1);
                    ah[4 * s + 2 * h + 1] = pk2(eB0, eB1);
                    al[4 * s + 2 * h + 0] = pk2(bf16_resid(eA0), bf16_resid(eA1));
                    al[4 * s + 2 * h + 1] = pk2(bf16_resid(eB0), bf16_resid(eB1));
                }
            }
        }
        __syncthreads();   // all warps done with X

        // ---- prefetch next x tile (overlaps all MMA work) ----
        {
            int tn = t + GRID;
            if (tn < NTILES) {
                const char* src = reinterpret_cast<const char*>(x) + (size_t)tn * TILE_M * NDIN * 4;
                #pragma unroll
                for (int k = 0; k < 4; k++) {
                    int idx = tid + NTHREADS * k;
                    if (idx < 800) cp16(sb + OFF_X + idx * 16, src + idx * 16);
                }
            }
            CP_COMMIT();
        }

        // ---- GEMM1: acc = xn @ w1 (3-term bf16 split), R5 schedule ----
        float acc[16][4];
        #pragma unroll
        for (int j = 0; j < 16; j++)
            #pragma unroll
            for (int r = 0; r < 4; r++) acc[j][r] = 0.0f;

        const uint4* f1 = reinterpret_cast<const uint4*>(smem + OFF_W1F);
        #pragma unroll
        for (int j = 0; j < 16; j++) {
            #pragma unroll
            for (int s = 0; s < 2; s++) {
                uint4 b = f1[(s * 16 + j) * 32 + lane];
                mma4(acc[j], ah[4*s], ah[4*s+1], ah[4*s+2], ah[4*s+3], b.x, b.y);
                mma4(acc[j], ah[4*s], ah[4*s+1], ah[4*s+2], ah[4*s+3], b.z, b.w);
                mma4(acc[j], al[4*s], al[4*s+1], al[4*s+2], al[4*s+3], b.x, b.y);
            }
        }

        // ---- bias + GELU + split: convert C frags IN PLACE into A2 frags ----
        // slot layout after conversion: acc[j][0]=hi(c0,c1) acc[j][1]=hi(c2,c3)
        //                               acc[j][2]=lo(c0,c1) acc[j][3]=lo(c2,c3)
        #pragma unroll
        for (int j = 0; j < 16; j++) {
            const float2 bb = *reinterpret_cast<const float2*>(b1s + 8 * j + q2);
            float g0 = gelu_f(acc[j][0] + bb.x);
            float g1 = gelu_f(acc[j][1] + bb.y);
            float g2 = gelu_f(acc[j][2] + bb.x);
            float g3 = gelu_f(acc[j][3] + bb.y);
            acc[j][0] = __uint_as_float(pk2(g0, g1));
            acc[j][1] = __uint_as_float(pk2(g2, g3));
            acc[j][2] = __uint_as_float(pk2(bf16_resid(g0), bf16_resid(g1)));
            acc[j][3] = __uint_as_float(pk2(bf16_resid(g2), bf16_resid(g3)));
        }

        // ---- GEMM2 in two j-halves (R5 schedule), stores overlap 2nd half ----
        const uint4* f2 = reinterpret_cast<const uint4*>(smem + OFF_W2F);
        const size_t row0 = (size_t)t * TILE_M + rA;
        #pragma unroll
        for (int half = 0; half < 2; half++) {
            float acc2[8][4];
            #pragma unroll
            for (int j = 0; j < 8; j++)
                #pragma unroll
                for (int r = 0; r < 4; r++) acc2[j][r] = 0.0f;

            #pragma unroll
            for (int j8 = 0; j8 < 8; j8++) {
                int j = 8 * half + j8;
                #pragma unroll
                for (int s = 0; s < 8; s++) {
                    uint4 b = f2[(s * 16 + j) * 32 + lane];
                    uint32_t h0 = __float_as_uint(acc[2*s][0]);
                    uint32_t h1 = __float_as_uint(acc[2*s][1]);
                    uint32_t h2 = __float_as_uint(acc[2*s+1][0]);
                    uint32_t h3 = __float_as_uint(acc[2*s+1][1]);
                    uint32_t l0 = __float_as_uint(acc[2*s][2]);
                    uint32_t l1 = __float_as_uint(acc[2*s][3]);
                    uint32_t l2 = __float_as_uint(acc[2*s+1][2]);
                    uint32_t l3 = __float_as_uint(acc[2*s+1][3]);
                    mma4(acc2[j8], h0, h1, h2, h3, b.x, b.y);
                    mma4(acc2[j8], h0, h1, h2, h3, b.z, b.w);
                    mma4(acc2[j8], l0, l1, l2, l3, b.x, b.y);
                }
            }

            #pragma unroll
            for (int j8 = 0; j8 < 8; j8++) {
                int j = 8 * half + j8;
                const float2 bb = *reinterpret_cast<const float2*>(b2s + 8 * j + q2);
                int col = 8 * j + q2;
                float2 o0 = make_float2(acc2[j8][0] + bb.x, acc2[j8][1] + bb.y);
                float2 o1 = make_float2(acc2[j8][2] + bb.x, acc2[j8][3] + bb.y);
                *reinterpret_cast<float2*>(out + row0 * NDP + col) = o0;
                *reinterpret_cast<float2*>(out + (row0 + 8) * NDP + col) = o1;
            }
        }
    }
}

extern "C" void kernel_launch(void* const* d_in, const int* in_sizes, int n_in,
                              void* d_out, int out_size) {
    (void)in_sizes; (void)n_in; (void)out_size;
    const float* x    = (const float*)d_in[0];
    const float* ln_g = (const float*)d_in[1];
    const float* ln_b = (const float*)d_in[2];
    const float* w1   = (const float*)d_in[3];
    const float* b1   = (const float*)d_in[4];
    const float* w2   = (const float*)d_in[5];
    const float* b2   = (const float*)d_in[6];
    float* out = (float*)d_out;

    cudaFuncSetAttribute(ip_mma_kernel, cudaFuncAttributeMaxDynamicSharedMemorySize, SMEM_TOTAL);
    ip_mma_kernel<<<GRID, NTHREADS, SMEM_TOTAL>>>(x, ln_g, ln_b, w1, b1, w2, b2, out);
}

// round 8
// speedup vs baseline: 1.9309x; 1.7783x over previous
#include <cuda_runtime.h>
#include <cuda_fp16.h>
#include <cstdint>
#include <math.h>

#define NDIN 25
#define NDP  128
#define NROWS (256*2048)
#define TILE_M 128
#define NTILES (NROWS/TILE_M)   // 4096
#define NTHREADS 256
#define GRID 148

// ---------------- SMEM layout (byte offsets) ----------------
#define OFF_X     0        // 12800 B  (128 rows x 25 f32)
#define OFF_XNHI  12800    // 10240 B  (128 rows x 80B stride: 32 fp16 = 64B used)
#define OFF_XNLO  23040    // 10240 B
#define OFF_W1F   33280    // 8192 B   [s2][j16][t32] uint2 = (bh0,bh1)
#define OFF_W2F   41472    // 32768 B  [s8][j16][t32] uint2
#define OFF_B1    74240    // 512
#define OFF_B2    74752    // 512
#define OFF_G     75264    // 128
#define OFF_BETA  75392    // 128
#define SMEM_TOTAL 75520

__device__ __forceinline__ uint32_t smem_u32(const void* p) {
    uint32_t a;
    asm("{ .reg .u64 t; cvta.to.shared.u64 t, %1; cvt.u32.u64 %0, t; }" : "=r"(a) : "l"(p));
    return a;
}

__device__ __forceinline__ void ldsm4(uint32_t* r, uint32_t addr) {
    asm volatile("ldmatrix.sync.aligned.m8n8.x4.shared.b16 {%0,%1,%2,%3}, [%4];"
                 : "=r"(r[0]), "=r"(r[1]), "=r"(r[2]), "=r"(r[3]) : "r"(addr));
}

__device__ __forceinline__ void mma_f16(float* c, const uint32_t* a, uint32_t b0, uint32_t b1) {
    asm volatile("mma.sync.aligned.m16n8k16.row.col.f32.f16.f16.f32 "
                 "{%0,%1,%2,%3}, {%4,%5,%6,%7}, {%8,%9}, {%0,%1,%2,%3};"
                 : "+f"(c[0]), "+f"(c[1]), "+f"(c[2]), "+f"(c[3])
                 : "r"(a[0]), "r"(a[1]), "r"(a[2]), "r"(a[3]), "r"(b0), "r"(b1));
}

__device__ __forceinline__ void cp16(uint32_t saddr, const void* g) {
    asm volatile("cp.async.ca.shared.global [%0], [%1], 16;" :: "r"(saddr), "l"(g));
}
#define CP_COMMIT() asm volatile("cp.async.commit_group;" ::: "memory")
#define CP_WAIT0()  asm volatile("cp.async.wait_group 0;" ::: "memory")

// pack two f32 -> fp16x2, first arg in LOW half (matches validated bf16 convention)
__device__ __forceinline__ uint32_t pk2h(float f_lo, float f_hi) {
    __half2 h = __floats2half2_rn(f_lo, f_hi);  // .x = f_lo (low), .y = f_hi (high)
    return *reinterpret_cast<uint32_t*>(&h);
}

// GELU, erf via Abramowitz-Stegun 7.1.26 (|eps_erf| <= 1.5e-7)
__device__ __forceinline__ float gelu_f(float v) {
    float z = fabsf(v) * 0.70710678118654752440f;
    float t = __fdividef(1.0f, fmaf(0.3275911f, z, 1.0f));
    float p = t * fmaf(t, fmaf(t, fmaf(t, fmaf(t, 1.061405429f, -1.453152027f),
                                       1.421413741f), -0.284496736f), 0.254829592f);
    float e = __expf(-z * z);
    float erfv = fmaf(-p, e, 1.0f);
    float erfs = (v < 0.0f) ? -erfv : erfv;
    return 0.5f * v * (1.0f + erfs);
}

__device__ __forceinline__ float f16_resid(float v) {
    return v - __half2float(__float2half_rn(v));
}

__global__ __launch_bounds__(NTHREADS, 1)
void ip_mma_kernel(const float* __restrict__ x,
                   const float* __restrict__ ln_g,
                   const float* __restrict__ ln_b,
                   const float* __restrict__ w1,
                   const float* __restrict__ b1,
                   const float* __restrict__ w2,
                   const float* __restrict__ b2,
                   float* __restrict__ out) {
    extern __shared__ char smem[];
    const uint32_t sb = smem_u32(smem);
    const int tid = threadIdx.x;
    const int lane = tid & 31;
    const int wid = tid >> 5;

    float* b1s = reinterpret_cast<float*>(smem + OFF_B1);
    float* b2s = reinterpret_cast<float*>(smem + OFF_B2);
    float* gs  = reinterpret_cast<float*>(smem + OFF_G);
    float* bs  = reinterpret_cast<float*>(smem + OFF_BETA);

    if (tid < 128) { b1s[tid] = b1[tid]; b2s[tid] = b2[tid]; }
    if (tid < NDIN) { gs[tid] = ln_g[tid]; bs[tid] = ln_b[tid]; }

    // ---- stage w1 fragments: B[n][k]=w1[k][n], fp16 hi only, uint2 ----
    uint2* w1f = reinterpret_cast<uint2*>(smem + OFF_W1F);
    for (int idx = tid; idx < 2 * 16 * 32; idx += NTHREADS) {
        int t = idx & 31, j = (idx >> 5) & 15, s = idx >> 9;
        int n = 8 * j + (t >> 2);
        int k0 = 16 * s + 2 * (t & 3);
        int kk[4] = {k0, k0 + 1, k0 + 8, k0 + 9};
        float v[4];
        #pragma unroll
        for (int q = 0; q < 4; q++) v[q] = (kk[q] < NDIN) ? w1[kk[q] * NDP + n] : 0.0f;
        uint2 val;
        val.x = pk2h(v[0], v[1]);
        val.y = pk2h(v[2], v[3]);
        w1f[(s * 16 + j) * 32 + t] = val;
    }
    // ---- stage w2 fragments: B[n][k]=w2[k][n], fp16 hi only, uint2 ----
    uint2* w2f = reinterpret_cast<uint2*>(smem + OFF_W2F);
    for (int idx = tid; idx < 8 * 16 * 32; idx += NTHREADS) {
        int t = idx & 31, j = (idx >> 5) & 15, s = idx >> 9;
        int n = 8 * j + (t >> 2);
        int k0 = 16 * s + 2 * (t & 3);
        uint2 val;
        val.x = pk2h(w2[k0 * NDP + n],       w2[(k0 + 1) * NDP + n]);
        val.y = pk2h(w2[(k0 + 8) * NDP + n], w2[(k0 + 9) * NDP + n]);
        w2f[(s * 16 + j) * 32 + t] = val;
    }
    __syncthreads();

    // per-warp ldmatrix base addresses for xn A-frags (16-row strip)
    const int m0 = wid * 16;
    const uint32_t addrAh = sb + OFF_XNHI + (uint32_t)(m0 + (lane & 15)) * 80 + ((lane >> 4) & 1) * 16;
    const uint32_t addrAl = sb + OFF_XNLO + (uint32_t)(m0 + (lane & 15)) * 80 + ((lane >> 4) & 1) * 16;

    // ---- prologue: prefetch first x tile ----
    {
        const char* src = reinterpret_cast<const char*>(x) + (size_t)blockIdx.x * TILE_M * NDIN * 4;
        #pragma unroll
        for (int k = 0; k < 4; k++) {
            int idx = tid + NTHREADS * k;
            if (idx < 800) cp16(sb + OFF_X + idx * 16, src + idx * 16);
        }
        CP_COMMIT();
    }

    for (int t = blockIdx.x; t < NTILES; t += GRID) {
        CP_WAIT0();
        __syncthreads();   // x tile ready; prior iter's xn reads done

        // ---- LayerNorm + fp16 split -> xn SMEM (threads 0..127, one row each) ----
        if (tid < 128) {
            const float* xr = reinterpret_cast<const float*>(smem + OFF_X) + tid * NDIN;
            float xv[NDIN];
            float s = 0.0f;
            #pragma unroll
            for (int k = 0; k < NDIN; k++) { xv[k] = xr[k]; s += xv[k]; }
            float mu = s * (1.0f / NDIN);
            float vv = 0.0f;
            #pragma unroll
            for (int k = 0; k < NDIN; k++) { float d = xv[k] - mu; vv += d * d; }
            float rstd = rsqrtf(vv * (1.0f / NDIN) + 1e-5f);
            uint32_t* dh = reinterpret_cast<uint32_t*>(smem + OFF_XNHI + tid * 80);
            uint32_t* dl = reinterpret_cast<uint32_t*>(smem + OFF_XNLO + tid * 80);
            #pragma unroll
            for (int c = 0; c < 16; c++) {
                int k0 = 2 * c, k1 = 2 * c + 1;
                float e0 = (k0 < NDIN) ? (xv[k0] - mu) * rstd * gs[k0] + bs[k0] : 0.0f;
                float e1 = (k1 < NDIN) ? (xv[k1] - mu) * rstd * gs[k1] + bs[k1] : 0.0f;
                dh[c] = pk2h(e0, e1);
                dl[c] = pk2h(f16_resid(e0), f16_resid(e1));
            }
        }
        __syncthreads();   // xn ready; x buffer free

        // ---- prefetch next x tile (overlaps all MMA work) ----
        {
            int tn = t + GRID;
            if (tn < NTILES) {
                const char* src = reinterpret_cast<const char*>(x) + (size_t)tn * TILE_M * NDIN * 4;
                #pragma unroll
                for (int k = 0; k < 4; k++) {
                    int idx = tid + NTHREADS * k;
                    if (idx < 800) cp16(sb + OFF_X + idx * 16, src + idx * 16);
                }
            }
            CP_COMMIT();
        }

        // ---- GEMM1: acc = xn @ w1 (2-term fp16: hi + x-residual) ----
        uint32_t ah[8], al[8];
        ldsm4(ah + 0, addrAh);      ldsm4(ah + 4, addrAh + 32);
        ldsm4(al + 0, addrAl);      ldsm4(al + 4, addrAl + 32);

        float acc[16][4];
        #pragma unroll
        for (int j = 0; j < 16; j++)
            #pragma unroll
            for (int r = 0; r < 4; r++) acc[j][r] = 0.0f;

        const uint2* f1 = reinterpret_cast<const uint2*>(smem + OFF_W1F);
        #pragma unroll
        for (int j = 0; j < 16; j++) {
            #pragma unroll
            for (int s = 0; s < 2; s++) {
                uint2 b = f1[(s * 16 + j) * 32 + lane];
                mma_f16(acc[j], ah + 4 * s, b.x, b.y);
                mma_f16(acc[j], al + 4 * s, b.x, b.y);
            }
        }

        // ---- bias + GELU + fp16 split: C frags -> GEMM2 A frags (registers) ----
        uint32_t a2h[8][4], a2l[8][4];
        #pragma unroll
        for (int j = 0; j < 16; j++) {
            const float2 bb = *reinterpret_cast<const float2*>(b1s + 8 * j + 2 * (lane & 3));
            float g0 = gelu_f(acc[j][0] + bb.x);
            float g1 = gelu_f(acc[j][1] + bb.y);
            float g2 = gelu_f(acc[j][2] + bb.x);
            float g3 = gelu_f(acc[j][3] + bb.y);
            int s = j >> 1, h = (j & 1) * 2;
            a2h[s][h + 0] = pk2h(g0, g1);
            a2h[s][h + 1] = pk2h(g2, g3);
            a2l[s][h + 0] = pk2h(f16_resid(g0), f16_resid(g1));
            a2l[s][h + 1] = pk2h(f16_resid(g2), f16_resid(g3));
        }

        // ---- GEMM2 in two j-halves (2-term fp16), stores overlap 2nd half ----
        const uint2* f2 = reinterpret_cast<const uint2*>(smem + OFF_W2F);
        const size_t row0 = (size_t)t * TILE_M + m0 + (lane >> 2);
        #pragma unroll
        for (int half = 0; half < 2; half++) {
            float acc2[8][4];
            #pragma unroll
            for (int j = 0; j < 8; j++)
                #pragma unroll
                for (int r = 0; r < 4; r++) acc2[j][r] = 0.0f;

            #pragma unroll
            for (int j8 = 0; j8 < 8; j8++) {
                int j = 8 * half + j8;
                #pragma unroll
                for (int s = 0; s < 8; s++) {
                    uint2 b = f2[(s * 16 + j) * 32 + lane];
                    mma_f16(acc2[j8], a2h[s], b.x, b.y);
                    mma_f16(acc2[j8], a2l[s], b.x, b.y);
                }
            }

            // epilogue for this half: +b2, float2 stores
            #pragma unroll
            for (int j8 = 0; j8 < 8; j8++) {
                int j = 8 * half + j8;
                const float2 bb = *reinterpret_cast<const float2*>(b2s + 8 * j + 2 * (lane & 3));
                int col = 8 * j + 2 * (lane & 3);
                float2 o0 = make_float2(acc2[j8][0] + bb.x, acc2[j8][1] + bb.y);
                float2 o1 = make_float2(acc2[j8][2] + bb.x, acc2[j8][3] + bb.y);
                *reinterpret_cast<float2*>(out + row0 * NDP + col) = o0;
                *reinterpret_cast<float2*>(out + (row0 + 8) * NDP + col) = o1;
            }
        }
    }
}

extern "C" void kernel_launch(void* const* d_in, const int* in_sizes, int n_in,
                              void* d_out, int out_size) {
    (void)in_sizes; (void)n_in; (void)out_size;
    const float* x    = (const float*)d_in[0];
    const float* ln_g = (const float*)d_in[1];
    const float* ln_b = (const float*)d_in[2];
    const float* w1   = (const float*)d_in[3];
    const float* b1   = (const float*)d_in[4];
    const float* w2   = (const float*)d_in[5];
    const float* b2   = (const float*)d_in[6];
    float* out = (float*)d_out;

    cudaFuncSetAttribute(ip_mma_kernel, cudaFuncAttributeMaxDynamicSharedMemorySize, SMEM_TOTAL);
    ip_mma_kernel<<<GRID, NTHREADS, SMEM_TOTAL>>>(x, ln_g, ln_b, w1, b1, w2, b2, out);
}

// round 9
// speedup vs baseline: 2.0452x; 1.0592x over previous
#include <cuda_runtime.h>
#include <cuda_fp16.h>
#include <cstdint>
#include <math.h>

#define NDIN 25
#define NDP  128
#define NROWS (256*2048)
#define TILE_M 256
#define NTILES (NROWS/TILE_M)   // 2048
#define NTHREADS 512
#define GRID 148

// ---------------- SMEM layout (byte offsets) ----------------
#define OFF_X     0        // 25600 B  (256 rows x 25 f32)
#define OFF_XNHI  25600    // 20480 B  (256 rows x 80B stride: 32 fp16 = 64B used)
#define OFF_XNLO  46080    // 20480 B
#define OFF_W1F   66560    // 8192 B   [s2][j16][t32] uint2 = (bh0,bh1)
#define OFF_W2F   74752    // 32768 B  [s8][j16][t32] uint2
#define OFF_B1    107520   // 512
#define OFF_B2    108032   // 512
#define OFF_G     108544   // 128
#define OFF_BETA  108672   // 128
#define SMEM_TOTAL 108800

__device__ __forceinline__ uint32_t smem_u32(const void* p) {
    uint32_t a;
    asm("{ .reg .u64 t; cvta.to.shared.u64 t, %1; cvt.u32.u64 %0, t; }" : "=r"(a) : "l"(p));
    return a;
}

__device__ __forceinline__ void ldsm4(uint32_t* r, uint32_t addr) {
    asm volatile("ldmatrix.sync.aligned.m8n8.x4.shared.b16 {%0,%1,%2,%3}, [%4];"
                 : "=r"(r[0]), "=r"(r[1]), "=r"(r[2]), "=r"(r[3]) : "r"(addr));
}

__device__ __forceinline__ void mma_f16(float* c, uint32_t a0, uint32_t a1, uint32_t a2,
                                        uint32_t a3, uint32_t b0, uint32_t b1) {
    asm volatile("mma.sync.aligned.m16n8k16.row.col.f32.f16.f16.f32 "
                 "{%0,%1,%2,%3}, {%4,%5,%6,%7}, {%8,%9}, {%0,%1,%2,%3};"
                 : "+f"(c[0]), "+f"(c[1]), "+f"(c[2]), "+f"(c[3])
                 : "r"(a0), "r"(a1), "r"(a2), "r"(a3), "r"(b0), "r"(b1));
}

__device__ __forceinline__ void cp16(uint32_t saddr, const void* g) {
    asm volatile("cp.async.ca.shared.global [%0], [%1], 16;" :: "r"(saddr), "l"(g));
}
#define CP_COMMIT() asm volatile("cp.async.commit_group;" ::: "memory")
#define CP_WAIT0()  asm volatile("cp.async.wait_group 0;" ::: "memory")

// pack two f32 -> fp16x2, first arg in LOW half
__device__ __forceinline__ uint32_t pk2h(float f_lo, float f_hi) {
    __half2 h = __floats2half2_rn(f_lo, f_hi);
    return *reinterpret_cast<uint32_t*>(&h);
}

// GELU, erf via Abramowitz-Stegun 7.1.26 (|eps_erf| <= 1.5e-7)
__device__ __forceinline__ float gelu_f(float v) {
    float z = fabsf(v) * 0.70710678118654752440f;
    float t = __fdividef(1.0f, fmaf(0.3275911f, z, 1.0f));
    float p = t * fmaf(t, fmaf(t, fmaf(t, fmaf(t, 1.061405429f, -1.453152027f),
                                       1.421413741f), -0.284496736f), 0.254829592f);
    float e = __expf(-z * z);
    float erfv = fmaf(-p, e, 1.0f);
    float erfs = (v < 0.0f) ? -erfv : erfv;
    return 0.5f * v * (1.0f + erfs);
}

__device__ __forceinline__ float f16_resid(float v) {
    return v - __half2float(__float2half_rn(v));
}

__global__ __launch_bounds__(NTHREADS, 1)
void ip_mma_kernel(const float* __restrict__ x,
                   const float* __restrict__ ln_g,
                   const float* __restrict__ ln_b,
                   const float* __restrict__ w1,
                   const float* __restrict__ b1,
                   const float* __restrict__ w2,
                   const float* __restrict__ b2,
                   float* __restrict__ out) {
    extern __shared__ char smem[];
    const uint32_t sb = smem_u32(smem);
    const int tid = threadIdx.x;
    const int lane = tid & 31;
    const int wid = tid >> 5;

    float* b1s = reinterpret_cast<float*>(smem + OFF_B1);
    float* b2s = reinterpret_cast<float*>(smem + OFF_B2);
    float* gs  = reinterpret_cast<float*>(smem + OFF_G);
    float* bs  = reinterpret_cast<float*>(smem + OFF_BETA);

    if (tid < 128) { b1s[tid] = b1[tid]; b2s[tid] = b2[tid]; }
    if (tid >= 128 && tid < 128 + NDIN) {
        gs[tid - 128] = ln_g[tid - 128];
        bs[tid - 128] = ln_b[tid - 128];
    }

    // ---- stage w1 fragments: B[n][k]=w1[k][n], fp16 hi only, uint2 ----
    uint2* w1f = reinterpret_cast<uint2*>(smem + OFF_W1F);
    for (int idx = tid; idx < 2 * 16 * 32; idx += NTHREADS) {
        int t = idx & 31, j = (idx >> 5) & 15, s = idx >> 9;
        int n = 8 * j + (t >> 2);
        int k0 = 16 * s + 2 * (t & 3);
        int kk[4] = {k0, k0 + 1, k0 + 8, k0 + 9};
        float v[4];
        #pragma unroll
        for (int q = 0; q < 4; q++) v[q] = (kk[q] < NDIN) ? w1[kk[q] * NDP + n] : 0.0f;
        uint2 val;
        val.x = pk2h(v[0], v[1]);
        val.y = pk2h(v[2], v[3]);
        w1f[(s * 16 + j) * 32 + t] = val;
    }
    // ---- stage w2 fragments: B[n][k]=w2[k][n], fp16 hi only, uint2 ----
    uint2* w2f = reinterpret_cast<uint2*>(smem + OFF_W2F);
    for (int idx = tid; idx < 8 * 16 * 32; idx += NTHREADS) {
        int t = idx & 31, j = (idx >> 5) & 15, s = idx >> 9;
        int n = 8 * j + (t >> 2);
        int k0 = 16 * s + 2 * (t & 3);
        uint2 val;
        val.x = pk2h(w2[k0 * NDP + n],       w2[(k0 + 1) * NDP + n]);
        val.y = pk2h(w2[(k0 + 8) * NDP + n], w2[(k0 + 9) * NDP + n]);
        w2f[(s * 16 + j) * 32 + t] = val;
    }
    __syncthreads();

    // per-warp ldmatrix base addresses for xn A-frags (16-row strip)
    const int m0 = wid * 16;
    const uint32_t addrAh = sb + OFF_XNHI + (uint32_t)(m0 + (lane & 15)) * 80 + ((lane >> 4) & 1) * 16;
    const uint32_t addrAl = sb + OFF_XNLO + (uint32_t)(m0 + (lane & 15)) * 80 + ((lane >> 4) & 1) * 16;

    // ---- prologue: prefetch first x tile (6400 f32 = 1600 float4) ----
    {
        const char* src = reinterpret_cast<const char*>(x) + (size_t)blockIdx.x * TILE_M * NDIN * 4;
        #pragma unroll
        for (int k = 0; k < 4; k++) {
            int idx = tid + NTHREADS * k;
            if (idx < 1600) cp16(sb + OFF_X + idx * 16, src + idx * 16);
        }
        CP_COMMIT();
    }

    for (int t = blockIdx.x; t < NTILES; t += GRID) {
        CP_WAIT0();
        __syncthreads();   // x tile ready; prior iter's xn reads done

        // ---- LayerNorm + fp16 split -> xn SMEM (threads 0..255, one row each) ----
        if (tid < TILE_M) {
            const float* xr = reinterpret_cast<const float*>(smem + OFF_X) + tid * NDIN;
            float xv[NDIN];
            float s = 0.0f;
            #pragma unroll
            for (int k = 0; k < NDIN; k++) { xv[k] = xr[k]; s += xv[k]; }
            float mu = s * (1.0f / NDIN);
            float vv = 0.0f;
            #pragma unroll
            for (int k = 0; k < NDIN; k++) { float d = xv[k] - mu; vv += d * d; }
            float rstd = rsqrtf(vv * (1.0f / NDIN) + 1e-5f);
            uint32_t* dh = reinterpret_cast<uint32_t*>(smem + OFF_XNHI + tid * 80);
            uint32_t* dl = reinterpret_cast<uint32_t*>(smem + OFF_XNLO + tid * 80);
            #pragma unroll
            for (int c = 0; c < 16; c++) {
                int k0 = 2 * c, k1 = 2 * c + 1;
                float e0 = (k0 < NDIN) ? (xv[k0] - mu) * rstd * gs[k0] + bs[k0] : 0.0f;
                float e1 = (k1 < NDIN) ? (xv[k1] - mu) * rstd * gs[k1] + bs[k1] : 0.0f;
                dh[c] = pk2h(e0, e1);
                dl[c] = pk2h(f16_resid(e0), f16_resid(e1));
            }
        }
        __syncthreads();   // xn ready; x buffer free

        // ---- prefetch next x tile (overlaps all MMA work) ----
        {
            int tn = t + GRID;
            if (tn < NTILES) {
                const char* src = reinterpret_cast<const char*>(x) + (size_t)tn * TILE_M * NDIN * 4;
                #pragma unroll
                for (int k = 0; k < 4; k++) {
                    int idx = tid + NTHREADS * k;
                    if (idx < 1600) cp16(sb + OFF_X + idx * 16, src + idx * 16);
                }
            }
            CP_COMMIT();
        }

        // ---- GEMM1: acc = xn @ w1 (2-term fp16: hi + x-residual) ----
        uint32_t ah[8], al[8];
        ldsm4(ah + 0, addrAh);      ldsm4(ah + 4, addrAh + 32);
        ldsm4(al + 0, addrAl);      ldsm4(al + 4, addrAl + 32);

        float acc[16][4];
        #pragma unroll
        for (int j = 0; j < 16; j++)
            #pragma unroll
            for (int r = 0; r < 4; r++) acc[j][r] = 0.0f;

        const uint2* f1 = reinterpret_cast<const uint2*>(smem + OFF_W1F);
        #pragma unroll
        for (int j = 0; j < 16; j++) {
            #pragma unroll
            for (int s = 0; s < 2; s++) {
                uint2 b = f1[(s * 16 + j) * 32 + lane];
                mma_f16(acc[j], ah[4*s], ah[4*s+1], ah[4*s+2], ah[4*s+3], b.x, b.y);
                mma_f16(acc[j], al[4*s], al[4*s+1], al[4*s+2], al[4*s+3], b.x, b.y);
            }
        }

        // ---- bias + GELU + fp16 split: convert C frags IN PLACE to A2 frags ----
        // layout: acc[j][0]=hi(c0,c1)  acc[j][1]=hi(c2,c3)
        //         acc[j][2]=lo(c0,c1)  acc[j][3]=lo(c2,c3)
        #pragma unroll
        for (int j = 0; j < 16; j++) {
            const float2 bb = *reinterpret_cast<const float2*>(b1s + 8 * j + 2 * (lane & 3));
            float g0 = gelu_f(acc[j][0] + bb.x);
            float g1 = gelu_f(acc[j][1] + bb.y);
            float g2 = gelu_f(acc[j][2] + bb.x);
            float g3 = gelu_f(acc[j][3] + bb.y);
            acc[j][0] = __uint_as_float(pk2h(g0, g1));
            acc[j][1] = __uint_as_float(pk2h(g2, g3));
            acc[j][2] = __uint_as_float(pk2h(f16_resid(g0), f16_resid(g1)));
            acc[j][3] = __uint_as_float(pk2h(f16_resid(g2), f16_resid(g3)));
        }

        // ---- GEMM2 in two j-halves (2-term fp16), stores overlap 2nd half ----
        const uint2* f2 = reinterpret_cast<const uint2*>(smem + OFF_W2F);
        const size_t row0 = (size_t)t * TILE_M + m0 + (lane >> 2);
        #pragma unroll
        for (int half = 0; half < 2; half++) {
            float acc2[8][4];
            #pragma unroll
            for (int j = 0; j < 8; j++)
                #pragma unroll
                for (int r = 0; r < 4; r++) acc2[j][r] = 0.0f;

            #pragma unroll
            for (int j8 = 0; j8 < 8; j8++) {
                int j = 8 * half + j8;
                #pragma unroll
                for (int s = 0; s < 8; s++) {
                    uint2 b = f2[(s * 16 + j) * 32 + lane];
                    uint32_t h0 = __float_as_uint(acc[2*s][0]);
                    uint32_t h1 = __float_as_uint(acc[2*s][1]);
                    uint32_t h2 = __float_as_uint(acc[2*s+1][0]);
                    uint32_t h3 = __float_as_uint(acc[2*s+1][1]);
                    uint32_t l0 = __float_as_uint(acc[2*s][2]);
                    uint32_t l1 = __float_as_uint(acc[2*s][3]);
                    uint32_t l2 = __float_as_uint(acc[2*s+1][2]);
                    uint32_t l3 = __float_as_uint(acc[2*s+1][3]);
                    mma_f16(acc2[j8], h0, h1, h2, h3, b.x, b.y);
                    mma_f16(acc2[j8], l0, l1, l2, l3, b.x, b.y);
                }
            }

            // epilogue for this half: +b2, float2 stores
            #pragma unroll
            for (int j8 = 0; j8 < 8; j8++) {
                int j = 8 * half + j8;
                const float2 bb = *reinterpret_cast<const float2*>(b2s + 8 * j + 2 * (lane & 3));
                int col = 8 * j + 2 * (lane & 3);
                float2 o0 = make_float2(acc2[j8][0] + bb.x, acc2[j8][1] + bb.y);
                float2 o1 = make_float2(acc2[j8][2] + bb.x, acc2[j8][3] + bb.y);
                *reinterpret_cast<float2*>(out + row0 * NDP + col) = o0;
                *reinterpret_cast<float2*>(out + (row0 + 8) * NDP + col) = o1;
            }
        }
    }
}

extern "C" void kernel_launch(void* const* d_in, const int* in_sizes, int n_in,
                              void* d_out, int out_size) {
    (void)in_sizes; (void)n_in; (void)out_size;
    const float* x    = (const float*)d_in[0];
    const float* ln_g = (const float*)d_in[1];
    const float* ln_b = (const float*)d_in[2];
    const float* w1   = (const float*)d_in[3];
    const float* b1   = (const float*)d_in[4];
    const float* w2   = (const float*)d_in[5];
    const float* b2   = (const float*)d_in[6];
    float* out = (float*)d_out;

    cudaFuncSetAttribute(ip_mma_kernel, cudaFuncAttributeMaxDynamicSharedMemorySize, SMEM_TOTAL);
    ip_mma_kernel<<<GRID, NTHREADS, SMEM_TOTAL>>>(x, ln_g, ln_b, w1, b1, w2, b2, out);
}

// round 12
// speedup vs baseline: 2.4344x; 1.1903x over previous
#include <cuda_runtime.h>
#include <cuda_fp16.h>
#include <cstdint>
#include <math.h>

#define NDIN 25
#define NDP  128
#define NROWS (256*2048)
#define TILE_M 256
#define NTILES (NROWS/TILE_M)   // 2048
#define NTHREADS 512
#define GRID 148
#define XBYTES (TILE_M*NDIN*4)  // 25600

// ---------------- SMEM layout (byte offsets) ----------------
#define OFF_X0    0        // 25600 B (x tile buffer 0)
#define OFF_X1    25600    // 25600 B (x tile buffer 1)
#define OFF_STAT  51200    // 2048 B  (256 x float2 {mu,rstd})
#define OFF_W1F   53248    // 8192 B  [s2][j16][t32] uint2
#define OFF_W2F   61440    // 32768 B [s8][j16][t32] uint2
#define OFF_B1    94208    // 512
#define OFF_B2    94720    // 512
#define OFF_G     95232    // 128
#define OFF_BETA  95360    // 128
#define SMEM_TOTAL 95488

__device__ __forceinline__ uint32_t smem_u32(const void* p) {
    uint32_t a;
    asm("{ .reg .u64 t; cvta.to.shared.u64 t, %1; cvt.u32.u64 %0, t; }" : "=r"(a) : "l"(p));
    return a;
}

__device__ __forceinline__ void mma_f16(float* c, uint32_t a0, uint32_t a1, uint32_t a2,
                                        uint32_t a3, uint32_t b0, uint32_t b1) {
    asm volatile("mma.sync.aligned.m16n8k16.row.col.f32.f16.f16.f32 "
                 "{%0,%1,%2,%3}, {%4,%5,%6,%7}, {%8,%9}, {%0,%1,%2,%3};"
                 : "+f"(c[0]), "+f"(c[1]), "+f"(c[2]), "+f"(c[3])
                 : "r"(a0), "r"(a1), "r"(a2), "r"(a3), "r"(b0), "r"(b1));
}

__device__ __forceinline__ void cp16(uint32_t saddr, const void* g) {
    asm volatile("cp.async.ca.shared.global [%0], [%1], 16;" :: "r"(saddr), "l"(g));
}
#define CP_COMMIT() asm volatile("cp.async.commit_group;" ::: "memory")
#define CP_WAIT0()  asm volatile("cp.async.wait_group 0;" ::: "memory")

__device__ __forceinline__ uint32_t pk2h(float f_lo, float f_hi) {
    __half2 h = __floats2half2_rn(f_lo, f_hi);
    return *reinterpret_cast<uint32_t*>(&h);
}

// GELU, erf via Abramowitz-Stegun 7.1.26 (|eps_erf| <= 1.5e-7)
__device__ __forceinline__ float gelu_f(float v) {
    float z = fabsf(v) * 0.70710678118654752440f;
    float t = __fdividef(1.0f, fmaf(0.3275911f, z, 1.0f));
    float p = t * fmaf(t, fmaf(t, fmaf(t, fmaf(t, 1.061405429f, -1.453152027f),
                                       1.421413741f), -0.284496736f), 0.254829592f);
    float e = __expf(-z * z);
    float erfv = fmaf(-p, e, 1.0f);
    float erfs = (v < 0.0f) ? -erfv : erfv;
    return 0.5f * v * (1.0f + erfs);
}

__device__ __forceinline__ float f16_resid(float v) {
    return v - __half2float(__float2half_rn(v));
}

__global__ __launch_bounds__(NTHREADS, 1)
void ip_mma_kernel(const float* __restrict__ x,
                   const float* __restrict__ ln_g,
                   const float* __restrict__ ln_b,
                   const float* __restrict__ w1,
                   const float* __restrict__ b1,
                   const float* __restrict__ w2,
                   const float* __restrict__ b2,
                   float* __restrict__ out) {
    extern __shared__ char smem[];
    const uint32_t sb = smem_u32(smem);
    const int tid = threadIdx.x;
    const int lane = tid & 31;
    const int wid = tid >> 5;

    float* b1s = reinterpret_cast<float*>(smem + OFF_B1);
    float* b2s = reinterpret_cast<float*>(smem + OFF_B2);
    float* gs  = reinterpret_cast<float*>(smem + OFF_G);
    float* bs  = reinterpret_cast<float*>(smem + OFF_BETA);
    float2* st = reinterpret_cast<float2*>(smem + OFF_STAT);

    if (tid < 128) { b1s[tid] = b1[tid]; b2s[tid] = b2[tid]; }
    if (tid >= 128 && tid < 128 + NDIN) {
        gs[tid - 128] = ln_g[tid - 128];
        bs[tid - 128] = ln_b[tid - 128];
    }

    // ---- stage w1 fragments (fp16 hi): B[n][k]=w1[k][n] ----
    uint2* w1f = reinterpret_cast<uint2*>(smem + OFF_W1F);
    for (int idx = tid; idx < 2 * 16 * 32; idx += NTHREADS) {
        int t = idx & 31, j = (idx >> 5) & 15, s = idx >> 9;
        int n = 8 * j + (t >> 2);
        int k0 = 16 * s + 2 * (t & 3);
        int kk[4] = {k0, k0 + 1, k0 + 8, k0 + 9};
        float v[4];
        #pragma unroll
        for (int q = 0; q < 4; q++) v[q] = (kk[q] < NDIN) ? w1[kk[q] * NDP + n] : 0.0f;
        uint2 val;
        val.x = pk2h(v[0], v[1]);
        val.y = pk2h(v[2], v[3]);
        w1f[(s * 16 + j) * 32 + t] = val;
    }
    // ---- stage w2 fragments (fp16 hi): B[n][k]=w2[k][n] ----
    uint2* w2f = reinterpret_cast<uint2*>(smem + OFF_W2F);
    for (int idx = tid; idx < 8 * 16 * 32; idx += NTHREADS) {
        int t = idx & 31, j = (idx >> 5) & 15, s = idx >> 9;
        int n = 8 * j + (t >> 2);
        int k0 = 16 * s + 2 * (t & 3);
        uint2 val;
        val.x = pk2h(w2[k0 * NDP + n],       w2[(k0 + 1) * NDP + n]);
        val.y = pk2h(w2[(k0 + 8) * NDP + n], w2[(k0 + 9) * NDP + n]);
        w2f[(s * 16 + j) * 32 + t] = val;
    }
    __syncthreads();

    const int m0 = wid * 16;
    const int q2 = 2 * (lane & 3);
    const int rA = m0 + (lane >> 2);   // in-tile rows this thread owns
    const int rB = rA + 8;

    // ---- preload per-thread gamma/beta for this thread's 8 k-slots ----
    float garr[2][2][2], bearr[2][2][2];
    #pragma unroll
    for (int s = 0; s < 2; s++)
        #pragma unroll
        for (int h = 0; h < 2; h++)
            #pragma unroll
            for (int par = 0; par < 2; par++) {
                int k = 16 * s + 8 * h + q2 + par;
                garr[s][h][par]  = (k < NDIN) ? gs[k] : 0.0f;
                bearr[s][h][par] = (k < NDIN) ? bs[k] : 0.0f;
            }

    // ---- prologue: prefetch first x tile into buffer 0 ----
    {
        const char* src = reinterpret_cast<const char*>(x) + (size_t)blockIdx.x * XBYTES;
        #pragma unroll
        for (int k = 0; k < 4; k++) {
            int idx = tid + NTHREADS * k;
            if (idx < XBYTES / 16) cp16(sb + OFF_X0 + idx * 16, src + idx * 16);
        }
        CP_COMMIT();
    }

    int bufsel = 0;
    for (int t = blockIdx.x; t < NTILES; t += GRID) {
        CP_WAIT0();
        __syncthreads();   // current x tile visible; prior-iter reads of other buffer done

        const float* Xc = reinterpret_cast<const float*>(smem + OFF_X0 + bufsel * XBYTES);

        // ---- prefetch next tile into the other buffer (overlaps everything) ----
        {
            int tn = t + GRID;
            if (tn < NTILES) {
                uint32_t dst = sb + OFF_X0 + (bufsel ^ 1) * XBYTES;
                const char* src = reinterpret_cast<const char*>(x) + (size_t)tn * XBYTES;
                #pragma unroll
                for (int k = 0; k < 4; k++) {
                    int idx = tid + NTHREADS * k;
                    if (idx < XBYTES / 16) cp16(dst + idx * 16, src + idx * 16);
                }
            }
            CP_COMMIT();
        }

        // ---- warp-local LN stats: 2 lanes per row, shfl-combined ----
        {
            int rloc = lane >> 1;              // 0..15
            int row = m0 + rloc;
            int half = lane & 1;
            const float* xr = Xc + row * NDIN;
            float sum = 0.0f, ssq = 0.0f;
            int k0 = half * 13, kcnt = 13 - half;   // even lane: k 0..12, odd: 13..24
            #pragma unroll
            for (int k = 0; k < 13; k++) {
                if (k < kcnt) {
                    float v = xr[k0 + k];
                    sum += v;
                    ssq = fmaf(v, v, ssq);
                }
            }
            sum += __shfl_xor_sync(0xffffffffu, sum, 1);
            ssq += __shfl_xor_sync(0xffffffffu, ssq, 1);
            float mu = sum * (1.0f / NDIN);
            float var = fmaf(-mu, mu, ssq * (1.0f / NDIN));
            float rstd = rsqrtf(fmaxf(var, 0.0f) + 1e-5f);
            if (half == 0) st[row] = make_float2(mu, rstd);
        }
        __syncwarp();

        // ---- build GEMM1 A-frags (hi + residual) directly from x ----
        uint32_t ah[8], al[8];
        {
            float2 sA = st[rA], sB = st[rB];
            #pragma unroll
            for (int s = 0; s < 2; s++) {
                #pragma unroll
                for (int h = 0; h < 2; h++) {
                    int k0 = 16 * s + 8 * h + q2;
                    float xa0 = (k0 < NDIN)     ? Xc[rA * NDIN + k0]     : 0.0f;
                    float xa1 = (k0 + 1 < NDIN) ? Xc[rA * NDIN + k0 + 1] : 0.0f;
                    float xb0 = (k0 < NDIN)     ? Xc[rB * NDIN + k0]     : 0.0f;
                    float xb1 = (k0 + 1 < NDIN) ? Xc[rB * NDIN + k0 + 1] : 0.0f;
                    float eA0 = fmaf((xa0 - sA.x) * sA.y, garr[s][h][0], bearr[s][h][0]);
                    float eA1 = fmaf((xa1 - sA.x) * sA.y, garr[s][h][1], bearr[s][h][1]);
                    float eB0 = fmaf((xb0 - sB.x) * sB.y, garr[s][h][0], bearr[s][h][0]);
                    float eB1 = fmaf((xb1 - sB.x) * sB.y, garr[s][h][1], bearr[s][h][1]);
                    int i = 4 * s + 2 * h;
                    ah[i + 0] = pk2h(eA0, eA1);
                    ah[i + 1] = pk2h(eB0, eB1);
                    al[i + 0] = pk2h(f16_resid(eA0), f16_resid(eA1));
                    al[i + 1] = pk2h(f16_resid(eB0), f16_resid(eB1));
                }
            }
        }

        // ---- GEMM1: acc = xn @ w1 (2-term fp16) ----
        float acc[16][4];
        #pragma unroll
        for (int j = 0; j < 16; j++)
            #pragma unroll
            for (int r = 0; r < 4; r++) acc[j][r] = 0.0f;

        const uint2* f1 = reinterpret_cast<const uint2*>(smem + OFF_W1F);
        #pragma unroll
        for (int j = 0; j < 16; j++) {
            #pragma unroll
            for (int s = 0; s < 2; s++) {
                uint2 b = f1[(s * 16 + j) * 32 + lane];
                mma_f16(acc[j], ah[4*s], ah[4*s+1], ah[4*s+2], ah[4*s+3], b.x, b.y);
                mma_f16(acc[j], al[4*s], al[4*s+1], al[4*s+2], al[4*s+3], b.x, b.y);
            }
        }

        // ---- bias + GELU, pack hi-only A2 frags (registers) ----
        uint32_t a2[8][4];
        #pragma unroll
        for (int j = 0; j < 16; j++) {
            const float2 bb = *reinterpret_cast<const float2*>(b1s + 8 * j + q2);
            float g0 = gelu_f(acc[j][0] + bb.x);
            float g1 = gelu_f(acc[j][1] + bb.y);
            float g2 = gelu_f(acc[j][2] + bb.x);
            float g3 = gelu_f(acc[j][3] + bb.y);
            int s = j >> 1, h = (j & 1) * 2;
            a2[s][h + 0] = pk2h(g0, g1);
            a2[s][h + 1] = pk2h(g2, g3);
        }

        // ---- GEMM2 (single-term fp16) in two j-halves, stores interleaved ----
        const uint2* f2 = reinterpret_cast<const uint2*>(smem + OFF_W2F);
        const size_t row0 = (size_t)t * TILE_M + rA;
        #pragma unroll
        for (int half = 0; half < 2; half++) {
            float acc2[8][4];
            #pragma unroll
            for (int j = 0; j < 8; j++)
                #pragma unroll
                for (int r = 0; r < 4; r++) acc2[j][r] = 0.0f;

            #pragma unroll
            for (int j8 = 0; j8 < 8; j8++) {
                int j = 8 * half + j8;
                #pragma unroll
                for (int s = 0; s < 8; s++) {
                    uint2 b = f2[(s * 16 + j) * 32 + lane];
                    mma_f16(acc2[j8], a2[s][0], a2[s][1], a2[s][2], a2[s][3], b.x, b.y);
                }
            }

            #pragma unroll
            for (int j8 = 0; j8 < 8; j8++) {
                int j = 8 * half + j8;
                const float2 bb = *reinterpret_cast<const float2*>(b2s + 8 * j + q2);
                int col = 8 * j + q2;
                float2 o0 = make_float2(acc2[j8][0] + bb.x, acc2[j8][1] + bb.y);
                float2 o1 = make_float2(acc2[j8][2] + bb.x, acc2[j8][3] + bb.y);
                *reinterpret_cast<float2*>(out + row0 * NDP + col) = o0;
                *reinterpret_cast<float2*>(out + (row0 + 8) * NDP + col) = o1;
            }
        }

        bufsel ^= 1;
    }
}

extern "C" void kernel_launch(void* const* d_in, const int* in_sizes, int n_in,
                              void* d_out, int out_size) {
    (void)in_sizes; (void)n_in; (void)out_size;
    const float* x    = (const float*)d_in[0];
    const float* ln_g = (const float*)d_in[1];
    const float* ln_b = (const float*)d_in[2];
    const float* w1   = (const float*)d_in[3];
    const float* b1   = (const float*)d_in[4];
    const float* w2   = (const float*)d_in[5];
    const float* b2   = (const float*)d_in[6];
    float* out = (float*)d_out;

    cudaFuncSetAttribute(ip_mma_kernel, cudaFuncAttributeMaxDynamicSharedMemorySize, SMEM_TOTAL);
    ip_mma_kernel<<<GRID, NTHREADS, SMEM_TOTAL>>>(x, ln_g, ln_b, w1, b1, w2, b2, out);
}

// round 13
// speedup vs baseline: 2.8619x; 1.1756x over previous
#include <cuda_runtime.h>
#include <cuda_fp16.h>
#include <cstdint>
#include <math.h>

#define NDIN 25
#define NDP  128
#define NROWS (256*2048)
#define TILE_M 256
#define NTILES (NROWS/TILE_M)   // 2048
#define NTHREADS 512
#define GRID 148
#define XBYTES (TILE_M*NDIN*4)  // 25600

// ---------------- SMEM layout (byte offsets) ----------------
#define OFF_X0    0        // 25600 B (x tile buffer 0)
#define OFF_X1    25600    // 25600 B (x tile buffer 1)
#define OFF_STAT  51200    // 2048 B  (256 x float2 {mu,rstd})
#define OFF_W1F   53248    // 8192 B  [s2][j16][t32] uint2  (k=25 row carries b1)
#define OFF_W2F   61440    // 32768 B [s8][j16][t32] uint2
#define OFF_B2    94208    // 512
#define OFF_G     94720    // 128
#define OFF_BETA  94848    // 128
#define SMEM_TOTAL 94976

__device__ __forceinline__ uint32_t smem_u32(const void* p) {
    uint32_t a;
    asm("{ .reg .u64 t; cvta.to.shared.u64 t, %1; cvt.u32.u64 %0, t; }" : "=r"(a) : "l"(p));
    return a;
}

__device__ __forceinline__ void mma_f16(float* c, uint32_t a0, uint32_t a1, uint32_t a2,
                                        uint32_t a3, uint32_t b0, uint32_t b1) {
    asm volatile("mma.sync.aligned.m16n8k16.row.col.f32.f16.f16.f32 "
                 "{%0,%1,%2,%3}, {%4,%5,%6,%7}, {%8,%9}, {%0,%1,%2,%3};"
                 : "+f"(c[0]), "+f"(c[1]), "+f"(c[2]), "+f"(c[3])
                 : "r"(a0), "r"(a1), "r"(a2), "r"(a3), "r"(b0), "r"(b1));
}

__device__ __forceinline__ void cp16(uint32_t saddr, const void* g) {
    asm volatile("cp.async.ca.shared.global [%0], [%1], 16;" :: "r"(saddr), "l"(g));
}
#define CP_COMMIT() asm volatile("cp.async.commit_group;" ::: "memory")
#define CP_WAIT0()  asm volatile("cp.async.wait_group 0;" ::: "memory")

__device__ __forceinline__ uint32_t pk2h(float f_lo, float f_hi) {
    __half2 h = __floats2half2_rn(f_lo, f_hi);
    return *reinterpret_cast<uint32_t*>(&h);
}

// Branch-free GELU: gelu(v) = 0.5(v+|v|) - 0.5|v| * p(t) * exp(-z^2),
// z = |v|/sqrt(2), t = 1/(1+0.47047 z)  (A&S 7.1.25, |eps_erf| <= 2.5e-5)
__device__ __forceinline__ float gelu_f(float v) {
    float av = fabsf(v);
    float z = av * 0.70710678118654752440f;
    float t = __fdividef(1.0f, fmaf(0.47047f, z, 1.0f));
    float p = t * fmaf(fmaf(0.7478556f, t, -0.0958798f), t, 0.3480242f);
    float e = __expf(-z * z);
    float w = 0.5f * av;
    float base = fmaf(0.5f, v, w);
    return fmaf(-p * e, w, base);
}

__global__ __launch_bounds__(NTHREADS, 1)
void ip_mma_kernel(const float* __restrict__ x,
                   const float* __restrict__ ln_g,
                   const float* __restrict__ ln_b,
                   const float* __restrict__ w1,
                   const float* __restrict__ b1,
                   const float* __restrict__ w2,
                   const float* __restrict__ b2,
                   float* __restrict__ out) {
    extern __shared__ char smem[];
    const uint32_t sb = smem_u32(smem);
    const int tid = threadIdx.x;
    const int lane = tid & 31;
    const int wid = tid >> 5;

    float* b2s = reinterpret_cast<float*>(smem + OFF_B2);
    float* gs  = reinterpret_cast<float*>(smem + OFF_G);
    float* bs  = reinterpret_cast<float*>(smem + OFF_BETA);
    float2* st = reinterpret_cast<float2*>(smem + OFF_STAT);

    if (tid < 128) b2s[tid] = b2[tid];
    if (tid >= 128 && tid < 128 + NDIN) {
        gs[tid - 128] = ln_g[tid - 128];
        bs[tid - 128] = ln_b[tid - 128];
    }

    // ---- stage w1 fragments (fp16): B[n][k]=w1[k][n]; k==25 row carries b1 ----
    uint2* w1f = reinterpret_cast<uint2*>(smem + OFF_W1F);
    for (int idx = tid; idx < 2 * 16 * 32; idx += NTHREADS) {
        int t = idx & 31, j = (idx >> 5) & 15, s = idx >> 9;
        int n = 8 * j + (t >> 2);
        int k0 = 16 * s + 2 * (t & 3);
        int kk[4] = {k0, k0 + 1, k0 + 8, k0 + 9};
        float v[4];
        #pragma unroll
        for (int q = 0; q < 4; q++)
            v[q] = (kk[q] < NDIN) ? w1[kk[q] * NDP + n]
                                  : ((kk[q] == NDIN) ? b1[n] : 0.0f);
        uint2 val;
        val.x = pk2h(v[0], v[1]);
        val.y = pk2h(v[2], v[3]);
        w1f[(s * 16 + j) * 32 + t] = val;
    }
    // ---- stage w2 fragments (fp16 hi): B[n][k]=w2[k][n] ----
    uint2* w2f = reinterpret_cast<uint2*>(smem + OFF_W2F);
    for (int idx = tid; idx < 8 * 16 * 32; idx += NTHREADS) {
        int t = idx & 31, j = (idx >> 5) & 15, s = idx >> 9;
        int n = 8 * j + (t >> 2);
        int k0 = 16 * s + 2 * (t & 3);
        uint2 val;
        val.x = pk2h(w2[k0 * NDP + n],       w2[(k0 + 1) * NDP + n]);
        val.y = pk2h(w2[(k0 + 8) * NDP + n], w2[(k0 + 9) * NDP + n]);
        w2f[(s * 16 + j) * 32 + t] = val;
    }
    __syncthreads();

    const int m0 = wid * 16;
    const int q2 = 2 * (lane & 3);
    const int rA = m0 + (lane >> 2);   // in-tile rows this thread owns
    const int rB = rA + 8;

    // ---- preload per-thread gamma/beta for this thread's 8 k-slots ----
    float garr[2][2][2], bearr[2][2][2];
    #pragma unroll
    for (int s = 0; s < 2; s++)
        #pragma unroll
        for (int h = 0; h < 2; h++)
            #pragma unroll
            for (int par = 0; par < 2; par++) {
                int k = 16 * s + 8 * h + q2 + par;
                garr[s][h][par]  = (k < NDIN) ? gs[k] : 0.0f;
                bearr[s][h][par] = (k < NDIN) ? bs[k] : ((k == NDIN) ? 1.0f : 0.0f);
            }
    // note: slot k==25 contributes A=1.0 (gamma=0, beta=1) -> picks up b1 row of w1f

    // ---- prologue: prefetch first x tile into buffer 0 ----
    {
        const char* src = reinterpret_cast<const char*>(x) + (size_t)blockIdx.x * XBYTES;
        #pragma unroll
        for (int k = 0; k < 4; k++) {
            int idx = tid + NTHREADS * k;
            if (idx < XBYTES / 16) cp16(sb + OFF_X0 + idx * 16, src + idx * 16);
        }
        CP_COMMIT();
    }

    int bufsel = 0;
    for (int t = blockIdx.x; t < NTILES; t += GRID) {
        CP_WAIT0();
        __syncthreads();   // current x tile visible; prior-iter reads of other buffer done

        const float* Xc = reinterpret_cast<const float*>(smem + OFF_X0 + bufsel * XBYTES);

        // ---- prefetch next tile into the other buffer ----
        {
            int tn = t + GRID;
            if (tn < NTILES) {
                uint32_t dst = sb + OFF_X0 + (bufsel ^ 1) * XBYTES;
                const char* src = reinterpret_cast<const char*>(x) + (size_t)tn * XBYTES;
                #pragma unroll
                for (int k = 0; k < 4; k++) {
                    int idx = tid + NTHREADS * k;
                    if (idx < XBYTES / 16) cp16(dst + idx * 16, src + idx * 16);
                }
            }
            CP_COMMIT();
        }

        // ---- warp-local LN stats: 2 lanes per row, shfl-combined ----
        {
            int rloc = lane >> 1;
            int row = m0 + rloc;
            int half = lane & 1;
            const float* xr = Xc + row * NDIN;
            float sum = 0.0f, ssq = 0.0f;
            int k0 = half * 13, kcnt = 13 - half;
            #pragma unroll
            for (int k = 0; k < 13; k++) {
                if (k < kcnt) {
                    float v = xr[k0 + k];
                    sum += v;
                    ssq = fmaf(v, v, ssq);
                }
            }
            sum += __shfl_xor_sync(0xffffffffu, sum, 1);
            ssq += __shfl_xor_sync(0xffffffffu, ssq, 1);
            float mu = sum * (1.0f / NDIN);
            float var = fmaf(-mu, mu, ssq * (1.0f / NDIN));
            float rstd = rsqrtf(fmaxf(var, 0.0f) + 1e-5f);
            if (half == 0) st[row] = make_float2(mu, rstd);
        }
        __syncwarp();

        // ---- build GEMM1 A-frags (fp16 hi only; k==25 slot = 1.0 for bias) ----
        uint32_t ah[8];
        {
            float2 sA = st[rA], sB = st[rB];
            #pragma unroll
            for (int s = 0; s < 2; s++) {
                #pragma unroll
                for (int h = 0; h < 2; h++) {
                    int k0 = 16 * s + 8 * h + q2;
                    float xa0 = (k0 < NDIN)     ? Xc[rA * NDIN + k0]     : 0.0f;
                    float xa1 = (k0 + 1 < NDIN) ? Xc[rA * NDIN + k0 + 1] : 0.0f;
                    float xb0 = (k0 < NDIN)     ? Xc[rB * NDIN + k0]     : 0.0f;
                    float xb1 = (k0 + 1 < NDIN) ? Xc[rB * NDIN + k0 + 1] : 0.0f;
                    float eA0 = fmaf((xa0 - sA.x) * sA.y, garr[s][h][0], bearr[s][h][0]);
                    float eA1 = fmaf((xa1 - sA.x) * sA.y, garr[s][h][1], bearr[s][h][1]);
                    float eB0 = fmaf((xb0 - sB.x) * sB.y, garr[s][h][0], bearr[s][h][0]);
                    float eB1 = fmaf((xb1 - sB.x) * sB.y, garr[s][h][1], bearr[s][h][1]);
                    int i = 4 * s + 2 * h;
                    ah[i + 0] = pk2h(eA0, eA1);
                    ah[i + 1] = pk2h(eB0, eB1);
                }
            }
        }

        // ---- GEMM1: acc = [xn|1] @ [w1;b1] (single-term fp16) ----
        float acc[16][4];
        #pragma unroll
        for (int j = 0; j < 16; j++)
            #pragma unroll
            for (int r = 0; r < 4; r++) acc[j][r] = 0.0f;

        const uint2* f1 = reinterpret_cast<const uint2*>(smem + OFF_W1F);
        #pragma unroll
        for (int j = 0; j < 16; j++) {
            #pragma unroll
            for (int s = 0; s < 2; s++) {
                uint2 b = f1[(s * 16 + j) * 32 + lane];
                mma_f16(acc[j], ah[4*s], ah[4*s+1], ah[4*s+2], ah[4*s+3], b.x, b.y);
            }
        }

        // ---- GELU (bias already folded), pack hi-only A2 frags ----
        uint32_t a2[8][4];
        #pragma unroll
        for (int j = 0; j < 16; j++) {
            float g0 = gelu_f(acc[j][0]);
            float g1 = gelu_f(acc[j][1]);
            float g2 = gelu_f(acc[j][2]);
            float g3 = gelu_f(acc[j][3]);
            int s = j >> 1, h = (j & 1) * 2;
            a2[s][h + 0] = pk2h(g0, g1);
            a2[s][h + 1] = pk2h(g2, g3);
        }

        // ---- GEMM2 (single-term fp16), acc2 initialized with b2 ----
        const uint2* f2 = reinterpret_cast<const uint2*>(smem + OFF_W2F);
        const size_t row0 = (size_t)t * TILE_M + rA;
        #pragma unroll
        for (int half = 0; half < 2; half++) {
            float acc2[8][4];
            #pragma unroll
            for (int j8 = 0; j8 < 8; j8++) {
                const float2 bb = *reinterpret_cast<const float2*>(b2s + 8 * (8 * half + j8) + q2);
                acc2[j8][0] = bb.x;
                acc2[j8][1] = bb.y;
                acc2[j8][2] = bb.x;
                acc2[j8][3] = bb.y;
            }

            #pragma unroll
            for (int j8 = 0; j8 < 8; j8++) {
                int j = 8 * half + j8;
                #pragma unroll
                for (int s = 0; s < 8; s++) {
                    uint2 b = f2[(s * 16 + j) * 32 + lane];
                    mma_f16(acc2[j8], a2[s][0], a2[s][1], a2[s][2], a2[s][3], b.x, b.y);
                }
            }

            #pragma unroll
            for (int j8 = 0; j8 < 8; j8++) {
                int col = 8 * (8 * half + j8) + q2;
                float2 o0 = make_float2(acc2[j8][0], acc2[j8][1]);
                float2 o1 = make_float2(acc2[j8][2], acc2[j8][3]);
                *reinterpret_cast<float2*>(out + row0 * NDP + col) = o0;
                *reinterpret_cast<float2*>(out + (row0 + 8) * NDP + col) = o1;
            }
        }

        bufsel ^= 1;
    }
}

extern "C" void kernel_launch(void* const* d_in, const int* in_sizes, int n_in,
                              void* d_out, int out_size) {
    (void)in_sizes; (void)n_in; (void)out_size;
    const float* x    = (const float*)d_in[0];
    const float* ln_g = (const float*)d_in[1];
    const float* ln_b = (const float*)d_in[2];
    const float* w1   = (const float*)d_in[3];
    const float* b1   = (const float*)d_in[4];
    const float* w2   = (const float*)d_in[5];
    const float* b2   = (const float*)d_in[6];
    float* out = (float*)d_out;

    cudaFuncSetAttribute(ip_mma_kernel, cudaFuncAttributeMaxDynamicSharedMemorySize, SMEM_TOTAL);
    ip_mma_kernel<<<GRID, NTHREADS, SMEM_TOTAL>>>(x, ln_g, ln_b, w1, b1, w2, b2, out);
}